// round 4
// baseline (speedup 1.0000x reference)
#include <cuda_runtime.h>
#include <cstdint>

// MeanAggregator: out[b, :] = (1/K) * sum_k embed[neigh_ids[b,k], :]
// B=8192, K=32, D=128, embed: [V=100000, 128] fp32.
// Pipeline: detect id width (int32 vs int64) -> normalize ids to int32 scratch
// -> warp-per-row gather-mean with fully unrolled K (32 independent LDG.128).

static constexpr int B = 8192;
static constexpr int K = 32;
static constexpr int D4 = 32;   // D/4
static constexpr long long V = 100000;
static constexpr int NIDS = B * K;  // 262144

__device__ int g_ids_are_64 = 0;
__device__ int g_idx[NIDS];  // normalized int32 indices (1 MB static scratch)

// If the buffer is genuinely int64, every value in [0, V). If it is int32 data
// read as int64, value = (id_hi<<32)|id_lo with id_hi random in [0,100000) ->
// out of range with prob ~1-1e-5 per element; 1024 checks make a false
// positive impossible in practice.
__global__ void detect_idx_width_kernel(const long long* __restrict__ ids_as64)
{
    if (threadIdx.x != 0) return;
    int ok64 = 1;
    for (int i = 0; i < 1024; ++i) {
        long long v = ids_as64[i];
        if (v < 0 || v >= V) { ok64 = 0; break; }
    }
    g_ids_are_64 = ok64;
}

__global__ __launch_bounds__(256) void normalize_idx_kernel(
    const void* __restrict__ neigh_ids_raw)
{
    const int wide = g_ids_are_64;
    int i = blockIdx.x * blockDim.x + threadIdx.x;
    const int stride = gridDim.x * blockDim.x;
    if (wide) {
        const long long* src = (const long long*)neigh_ids_raw;
        for (; i < NIDS; i += stride) g_idx[i] = (int)src[i];
    } else {
        const int* src = (const int*)neigh_ids_raw;
        for (; i < NIDS; i += stride) g_idx[i] = src[i];
    }
}

__global__ __launch_bounds__(128) void mean_agg_kernel(
    const float4* __restrict__ embed,          // [V, D4]
    float4* __restrict__ out)                  // [B, D4]
{
    const int warp_global = (blockIdx.x * blockDim.x + threadIdx.x) >> 5;
    const int lane = threadIdx.x & 31;

    // Lane k holds the k-th neighbor id for this row.
    int my_id = g_idx[warp_global * K + lane];

    float4 acc = make_float4(0.f, 0.f, 0.f, 0.f);

#pragma unroll
    for (int k = 0; k < K; ++k) {
        int nid = __shfl_sync(0xffffffffu, my_id, k);
        float4 v = __ldg(&embed[(unsigned)nid * D4 + lane]);
        acc.x += v.x;
        acc.y += v.y;
        acc.z += v.z;
        acc.w += v.w;
    }

    const float inv_k = 1.0f / (float)K;
    acc.x *= inv_k;
    acc.y *= inv_k;
    acc.z *= inv_k;
    acc.w *= inv_k;

    out[warp_global * D4 + lane] = acc;
}

extern "C" void kernel_launch(void* const* d_in, const int* in_sizes, int n_in,
                              void* d_out, int out_size)
{
    // Identify inputs by element count, not position.
    const void* neigh_ids = d_in[0];
    const void* embed = d_in[1];
    if (n_in >= 2) {
        if (in_sizes[0] == (int)(V * 128) || in_sizes[1] == NIDS) {
            embed = d_in[0];
            neigh_ids = d_in[1];
        }
    }

    detect_idx_width_kernel<<<1, 32>>>((const long long*)neigh_ids);
    normalize_idx_kernel<<<256, 256>>>(neigh_ids);

    // 128-thread blocks: 2048 blocks over 148 SMs -> ~13.8 blocks/SM,
    // ~7% ragged tail instead of ~14% with 256-thread blocks.
    const int threads = 128;                 // 4 warps/block
    const int blocks = B / (threads / 32);   // 2048
    mean_agg_kernel<<<blocks, threads>>>((const float4*)embed, (float4*)d_out);
}

// round 8
// speedup vs baseline: 1.1629x; 1.1629x over previous
#include <cuda_runtime.h>
#include <cstdint>

// MeanAggregator: out[b, :] = (1/K) * sum_k embed[neigh_ids[b,k], :]
// B=8192, K=32, D=128, embed: [V=100000, 128] fp32.
//
// Single kernel. Warp-per-row; lane k holds neighbor id k; __shfl broadcast;
// 32 independent coalesced LDG.128 per row (full K unroll -> high MLP).
//
// Index width (JAX delivers int32 despite the int64 reference signature when
// x64 is off) is detected inline via a SAFE uniform probe: the first 32 int64
// words of the buffer (256 B — in-bounds under either width). int32 data has
// random odd words -> fails the [0,V) range vote with certainty; genuine
// int64 data always passes. Same verdict in every warp (uniform branch).

static constexpr int B = 8192;
static constexpr int K = 32;
static constexpr int D4 = 32;           // D/4
static constexpr long long V = 100000;
static constexpr int NIDS = B * K;

__global__ __launch_bounds__(128) void mean_agg_kernel(
    const void* __restrict__ neigh_ids_raw,    // [B, K] int32 or int64
    const float4* __restrict__ embed,          // [V, D4]
    float4* __restrict__ out)                  // [B, D4]
{
    const int warp_global = (blockIdx.x * blockDim.x + threadIdx.x) >> 5;
    const int lane = threadIdx.x & 31;

    // Uniform width probe on the first 256 bytes (always in-bounds).
    long long probe = ((const long long*)neigh_ids_raw)[lane];
    bool in_range = (probe >= 0) && (probe < V);
    bool ids_are_64 = __all_sync(0xffffffffu, in_range);

    // Lane k holds the k-th neighbor id for this row, at the detected width.
    int my_id;
    if (ids_are_64) {
        my_id = (int)((const long long*)neigh_ids_raw)[warp_global * K + lane];
    } else {
        my_id = ((const int*)neigh_ids_raw)[warp_global * K + lane];
    }

    float4 acc = make_float4(0.f, 0.f, 0.f, 0.f);

#pragma unroll
    for (int k = 0; k < K; ++k) {
        unsigned nid = (unsigned)__shfl_sync(0xffffffffu, my_id, k);
        float4 v = __ldg(&embed[nid * D4 + lane]);
        acc.x += v.x;
        acc.y += v.y;
        acc.z += v.z;
        acc.w += v.w;
    }

    const float inv_k = 1.0f / (float)K;
    acc.x *= inv_k;
    acc.y *= inv_k;
    acc.z *= inv_k;
    acc.w *= inv_k;

    out[warp_global * D4 + lane] = acc;
}

extern "C" void kernel_launch(void* const* d_in, const int* in_sizes, int n_in,
                              void* d_out, int out_size)
{
    // Identify inputs by element count, not position.
    const void* neigh_ids = d_in[0];
    const void* embed = d_in[1];
    if (n_in >= 2) {
        if (in_sizes[0] == (int)(V * 128) || in_sizes[1] == NIDS) {
            embed = d_in[0];
            neigh_ids = d_in[1];
        }
    }

    // 128-thread blocks: 2048 blocks -> finer tail quantum across 148 SMs.
    const int threads = 128;                 // 4 warps/block
    const int blocks = B / (threads / 32);   // 2048
    mean_agg_kernel<<<blocks, threads>>>(neigh_ids, (const float4*)embed,
                                         (float4*)d_out);
}